// round 15
// baseline (speedup 1.0000x reference)
#include <cuda_runtime.h>

namespace {

using u64 = unsigned long long;

constexpr int B  = 4096;
constexpr int T  = 1000;

constexpr int WARPS = 4;             // 128 threads/block
constexpr int EPW   = 2;             // batch elements per warp
constexpr int EPB   = WARPS * EPW;   // 8
constexpr int NBLK  = B / EPB;       // 512 blocks -> 4 blocks/SM binding, single wave
constexpr int RS    = 12;            // padded row stride (floats)
constexpr int EPP   = EPB + EPW;     // 10 rows (layer stride 120 ≡ 24 mod 32: bank-disjoint)

constexpr int HOFF = 3 * EPP * RS;   // 360
constexpr int XOFF = EPP * RS;       // 120

// ---- packed f32x2 helpers ----
__device__ __forceinline__ u64 fma2(u64 a, u64 b, u64 c) {
    u64 d;
    asm("fma.rn.f32x2 %0, %1, %2, %3;" : "=l"(d) : "l"(a), "l"(b), "l"(c));
    return d;
}
__device__ __forceinline__ u64 pack2(float lo, float hi) {
    u64 d;
    asm("mov.b64 %0, {%1, %2};" : "=l"(d) : "f"(lo), "f"(hi));
    return d;
}
__device__ __forceinline__ float hsum2(u64 v) {
    float lo, hi;
    asm("mov.b64 {%0, %1}, %2;" : "=f"(lo), "=f"(hi) : "l"(v));
    return lo + hi;
}
__device__ __forceinline__ float tanhapx(float v) {
    float y;
    asm("tanh.approx.f32 %0, %1;" : "=f"(y) : "f"(v));
    return y;
}
// sigmoid(x) with argument pre-scaled by 0.5 (folded into weights/biases)
__device__ __forceinline__ float sighalf(float a) {
    return fmaf(0.5f, tanhapx(a), 0.5f);
}

__device__ __forceinline__ void load10p(const float* __restrict__ p, u64* v) {
    ulonglong2 a = *reinterpret_cast<const ulonglong2*>(p);
    ulonglong2 b = *reinterpret_cast<const ulonglong2*>(p + 4);
    v[0] = a.x; v[1] = a.y; v[2] = b.x; v[3] = b.y;
    v[4] = *reinterpret_cast<const u64*>(p + 8);
}

__global__ void __launch_bounds__(WARPS * 32, 4)
gru3_pipe2e(const float* __restrict__ x,
            const float* __restrict__ Wih0, const float* __restrict__ Whh0,
            const float* __restrict__ bih0, const float* __restrict__ bhh0,
            const float* __restrict__ Wih1, const float* __restrict__ Whh1,
            const float* __restrict__ bih1, const float* __restrict__ bhh1,
            const float* __restrict__ Wih2, const float* __restrict__ Whh2,
            const float* __restrict__ bih2, const float* __restrict__ bhh2,
            const float* __restrict__ Wout, const float* __restrict__ bout,
            float* __restrict__ out)
{
    __shared__ __align__(16) float s_h[2][3][EPP][RS];
    __shared__ __align__(16) float s_x[2][EPP][RS];

    const int tid  = threadIdx.x;
    const int lane = tid & 31;
    const int warp = tid >> 5;

    int  l = lane / 10;            // layer owned by this lane
    int  j = lane - l * 10;        // hidden unit owned by this lane
    const bool lane_ok = (lane < 30);
    if (!lane_ok) { l = 2; j = 9; }   // dummies: real weights, scratch rows

    for (int idx = tid; idx < 2 * HOFF; idx += WARPS * 32) (&s_h[0][0][0][0])[idx] = 0.0f;
    for (int idx = tid; idx < 2 * XOFF; idx += WARPS * 32) (&s_x[0][0][0])[idx]    = 0.0f;

    // ---- this lane's layer weights -> registers (r/z rows pre-scaled by 0.5) ----
    const float* Wi = (l == 0) ? Wih0 : (l == 1) ? Wih1 : Wih2;
    const float* Wh = (l == 0) ? Whh0 : (l == 1) ? Whh1 : Whh2;
    const float* bi = (l == 0) ? bih0 : (l == 1) ? bih1 : bih2;
    const float* bh = (l == 0) ? bhh0 : (l == 1) ? bhh1 : bhh2;
    const int in_w = (l == 0) ? 3 : 10;

    u64 wi[3][5], wh[3][5];
#pragma unroll
    for (int g = 0; g < 3; g++) {
        const int row = g * 10 + j;
        const float sc = (g < 2) ? 0.5f : 1.0f;
#pragma unroll
        for (int k = 0; k < 5; k++) {
            const int c0 = 2 * k, c1 = 2 * k + 1;
            float f0 = (c0 < in_w) ? Wi[row * in_w + c0] * sc : 0.0f;
            float f1 = (c1 < in_w) ? Wi[row * in_w + c1] * sc : 0.0f;
            wi[g][k] = pack2(f0, f1);
            wh[g][k] = pack2(Wh[row * 10 + c0] * sc, Wh[row * 10 + c1] * sc);
        }
    }
    // Bias packs: accumulator initializers (bias in lo half, 0 in hi).
    const u64 bRp = pack2(0.5f * (bi[j] + bh[j]), 0.f);
    const u64 bZp = pack2(0.5f * (bi[10 + j] + bh[10 + j]), 0.f);
    const u64 bNp = pack2(bi[20 + j], 0.f);
    const u64 bHp = pack2(bh[20 + j], 0.f);

    // Per-element row pointers (buffer 0; buffer 1 via +IOFF/+HOFF).
    const int ebe0 = lane_ok ? warp * EPW : EPB;
    const float* in_p[EPW];
    const float* rec_p[EPW];
    float*       wr_p[EPW];
#pragma unroll
    for (int e = 0; e < EPW; e++) {
        in_p[e]  = (l == 0) ? &s_x[0][ebe0 + e][0] : &s_h[0][l - 1][ebe0 + e][0];
        rec_p[e] = &s_h[0][l][ebe0 + e][0];
        wr_p[e]  = &s_h[0][l][ebe0 + e][j];
    }
    const int IOFF = (l == 0) ? XOFF : HOFF;

    // Branchless x staging: lanes 0..5 own real (pe,pc); lanes 6..31 duplicate
    // addresses (coalescer dedups the LDG) and store to scratch rows 8/9.
    const int pe_d = (lane / 3) % EPW;      // duplicated element pattern
    const int pc_d = lane % 3;              // component
    const int egp  = blockIdx.x * EPB + warp * EPW + pe_d;   // always < B (B % EPB == 0)
    const float* xg = x + (size_t)egp * (T * 3) + pc_d;
    const int sx_row = (lane < EPW * 3) ? (warp * EPW + pe_d) : (EPB + (lane & 1));
    float* sxp = &s_x[0][sx_row][pc_d];

    __syncthreads();

    // pipeline init: x[0] -> buf1 (read at s=0); xreg = x[1] (stored during s=0).
    float xreg;
    sxp[XOFF] = xg[0];
    xreg = xg[3];
    __syncwarp();

    float myh[EPW] = {0.f, 0.f};

    auto step = [&](int s, int bw, bool edge) {
        const int br  = bw ^ 1;
        const int iro = br ? IOFF : 0;
        const int rro = br ? HOFF : 0;
        const int wo  = bw ? HOFF : 0;

        // branchless x staging (write buffer only read next step, after sync)
        sxp[bw ? XOFF : 0] = xreg;                   // stage x[s+1]
        xreg = xg[min(s + 2, T - 1) * 3];            // prefetch x[s+2]

        // ---- elem 0: dots + r/z MUFUs; tanh tail deferred past elem 1's dots ----
        float r0, z0, xn0, hh0;
        {
            u64 iv[5], hv[5];
            load10p(in_p[0] + iro, iv);
            load10p(rec_p[0] + rro, hv);
            u64 aR = bRp;
#pragma unroll
            for (int k = 0; k < 5; k++) aR = fma2(wi[0][k], iv[k], aR);
#pragma unroll
            for (int k = 0; k < 5; k++) aR = fma2(wh[0][k], hv[k], aR);
            r0 = sighalf(hsum2(aR));                  // MUFU e0-r in flight
            u64 aZ = bZp;
#pragma unroll
            for (int k = 0; k < 5; k++) aZ = fma2(wi[1][k], iv[k], aZ);
#pragma unroll
            for (int k = 0; k < 5; k++) aZ = fma2(wh[1][k], hv[k], aZ);
            z0 = sighalf(hsum2(aZ));                  // MUFU e0-z in flight
            u64 aN = bNp, aH = bHp;
#pragma unroll
            for (int k = 0; k < 5; k++) {
                aN = fma2(wi[2][k], iv[k], aN);
                aH = fma2(wh[2][k], hv[k], aH);
            }
            xn0 = hsum2(aN);
            hh0 = hsum2(aH);
        }
        // ---- elem 1: dots (e0's MUFU latency hides under this fma stream) ----
        float r1, z1, xn1, hh1;
        {
            u64 iv[5], hv[5];
            load10p(in_p[1] + iro, iv);
            load10p(rec_p[1] + rro, hv);
            u64 aR = bRp;
#pragma unroll
            for (int k = 0; k < 5; k++) aR = fma2(wi[0][k], iv[k], aR);
#pragma unroll
            for (int k = 0; k < 5; k++) aR = fma2(wh[0][k], hv[k], aR);
            r1 = sighalf(hsum2(aR));                  // MUFU e1-r
            u64 aZ = bZp;
#pragma unroll
            for (int k = 0; k < 5; k++) aZ = fma2(wi[1][k], iv[k], aZ);
#pragma unroll
            for (int k = 0; k < 5; k++) aZ = fma2(wh[1][k], hv[k], aZ);
            z1 = sighalf(hsum2(aZ));                  // MUFU e1-z
            u64 aN = bNp, aH = bHp;
#pragma unroll
            for (int k = 0; k < 5; k++) {
                aN = fma2(wi[2][k], iv[k], aN);
                aH = fma2(wh[2][k], hv[k], aH);
            }
            xn1 = hsum2(aN);
            hh1 = hsum2(aH);
        }
        // ---- tails: the two tanhs overlap each other and e1's z MUFU ----
        const float n0 = tanhapx(fmaf(r0, hh0, xn0));
        const float n1 = tanhapx(fmaf(r1, hh1, xn1));
        const float hn0 = n0 + z0 * (myh[0] - n0);
        const float hn1 = n1 + z1 * (myh[1] - n1);
        if (!edge || ((unsigned)(s - l) < (unsigned)T)) {
            myh[0] = hn0;  wr_p[0][wo] = hn0;
            myh[1] = hn1;  wr_p[1][wo] = hn1;
        }
        __syncwarp();
    };

    step(0, 0, true);
    step(1, 1, true);
#pragma unroll 1
    for (int s = 2; s < T; s += 2) {      // s = 2 .. 999, unconditional body
        step(s,     0, false);
        step(s + 1, 1, false);
    }
    step(T,     0, true);                 // s = 1000
    step(T + 1, 1, true);                 // s = 1001 -> final h2 in buffer 1

    // Output head: lanes (l==2, j<EPW) each dot one element's final h2 row.
    if (l == 2 && j < EPW && lane_ok) {
        const int eg = blockIdx.x * EPB + ebe0 + j;
        const float* hp = rec_p[j] + HOFF;            // s_h[1][2][ebe0+j]
        float acc = bout[0];
#pragma unroll
        for (int k = 0; k < 10; k++) acc = fmaf(Wout[k], hp[k], acc);
        out[eg] = acc;
    }
}

} // namespace

extern "C" void kernel_launch(void* const* d_in, const int* in_sizes, int n_in,
                              void* d_out, int out_size) {
    const float* x    = (const float*)d_in[0];
    const float* Wih0 = (const float*)d_in[1];
    const float* Whh0 = (const float*)d_in[2];
    const float* bih0 = (const float*)d_in[3];
    const float* bhh0 = (const float*)d_in[4];
    const float* Wih1 = (const float*)d_in[5];
    const float* Whh1 = (const float*)d_in[6];
    const float* bih1 = (const float*)d_in[7];
    const float* bhh1 = (const float*)d_in[8];
    const float* Wih2 = (const float*)d_in[9];
    const float* Whh2 = (const float*)d_in[10];
    const float* bih2 = (const float*)d_in[11];
    const float* bhh2 = (const float*)d_in[12];
    const float* Wout = (const float*)d_in[13];
    const float* bout = (const float*)d_in[14];
    float* out = (float*)d_out;

    gru3_pipe2e<<<NBLK, WARPS * 32>>>(x, Wih0, Whh0, bih0, bhh0,
                                      Wih1, Whh1, bih1, bhh1,
                                      Wih2, Whh2, bih2, bhh2,
                                      Wout, bout, out);
}

// round 16
// speedup vs baseline: 1.0046x; 1.0046x over previous
#include <cuda_runtime.h>

namespace {

using u64 = unsigned long long;

constexpr int B  = 4096;
constexpr int T  = 1000;

constexpr int WARPS = 4;             // 128 threads/block
constexpr int EPW   = 2;             // batch elements per warp
constexpr int EPB   = WARPS * EPW;   // 8
constexpr int NBLK  = B / EPB;       // 512 blocks -> 4 blocks/SM binding, single wave
constexpr int RS    = 12;            // padded row stride (floats)
constexpr int EPP   = EPB + EPW;     // 10 rows (layer stride 120 ≡ 24 mod 32: bank-disjoint)

constexpr int HOFF = 3 * EPP * RS;   // 360
constexpr int XOFF = EPP * RS;       // 120

// ---- packed f32x2 helpers ----
__device__ __forceinline__ u64 fma2(u64 a, u64 b, u64 c) {
    u64 d;
    asm("fma.rn.f32x2 %0, %1, %2, %3;" : "=l"(d) : "l"(a), "l"(b), "l"(c));
    return d;
}
__device__ __forceinline__ u64 pack2(float lo, float hi) {
    u64 d;
    asm("mov.b64 %0, {%1, %2};" : "=l"(d) : "f"(lo), "f"(hi));
    return d;
}
__device__ __forceinline__ float hsum2(u64 v) {
    float lo, hi;
    asm("mov.b64 {%0, %1}, %2;" : "=f"(lo), "=f"(hi) : "l"(v));
    return lo + hi;
}
__device__ __forceinline__ float tanhapx(float v) {
    float y;
    asm("tanh.approx.f32 %0, %1;" : "=f"(y) : "f"(v));
    return y;
}
// sigmoid(x) with argument pre-scaled by 0.5 (folded into weights/biases)
__device__ __forceinline__ float sighalf(float a) {
    return fmaf(0.5f, tanhapx(a), 0.5f);
}

__device__ __forceinline__ void load10p(const float* __restrict__ p, u64* v) {
    ulonglong2 a = *reinterpret_cast<const ulonglong2*>(p);
    ulonglong2 b = *reinterpret_cast<const ulonglong2*>(p + 4);
    v[0] = a.x; v[1] = a.y; v[2] = b.x; v[3] = b.y;
    v[4] = *reinterpret_cast<const u64*>(p + 8);
}

__global__ void __launch_bounds__(WARPS * 32, 4)
gru3_pipe2f(const float* __restrict__ x,
            const float* __restrict__ Wih0, const float* __restrict__ Whh0,
            const float* __restrict__ bih0, const float* __restrict__ bhh0,
            const float* __restrict__ Wih1, const float* __restrict__ Whh1,
            const float* __restrict__ bih1, const float* __restrict__ bhh1,
            const float* __restrict__ Wih2, const float* __restrict__ Whh2,
            const float* __restrict__ bih2, const float* __restrict__ bhh2,
            const float* __restrict__ Wout, const float* __restrict__ bout,
            float* __restrict__ out)
{
    __shared__ __align__(16) float s_h[2][3][EPP][RS];
    __shared__ __align__(16) float s_x[2][EPP][RS];

    const int tid  = threadIdx.x;
    const int lane = tid & 31;
    const int warp = tid >> 5;

    int  l = lane / 10;            // layer owned by this lane
    int  j = lane - l * 10;        // hidden unit owned by this lane
    const bool lane_ok = (lane < 30);
    if (!lane_ok) { l = 2; j = 9; }   // dummies: real weights, scratch rows

    for (int idx = tid; idx < 2 * HOFF; idx += WARPS * 32) (&s_h[0][0][0][0])[idx] = 0.0f;
    for (int idx = tid; idx < 2 * XOFF; idx += WARPS * 32) (&s_x[0][0][0])[idx]    = 0.0f;

    // ---- this lane's layer weights -> registers (r/z rows pre-scaled by 0.5) ----
    const float* Wi = (l == 0) ? Wih0 : (l == 1) ? Wih1 : Wih2;
    const float* Wh = (l == 0) ? Whh0 : (l == 1) ? Whh1 : Whh2;
    const float* bi = (l == 0) ? bih0 : (l == 1) ? bih1 : bih2;
    const float* bh = (l == 0) ? bhh0 : (l == 1) ? bhh1 : bhh2;
    const int in_w = (l == 0) ? 3 : 10;

    u64 wi[3][5], wh[3][5];
#pragma unroll
    for (int g = 0; g < 3; g++) {
        const int row = g * 10 + j;
        const float sc = (g < 2) ? 0.5f : 1.0f;
#pragma unroll
        for (int k = 0; k < 5; k++) {
            const int c0 = 2 * k, c1 = 2 * k + 1;
            float f0 = (c0 < in_w) ? Wi[row * in_w + c0] * sc : 0.0f;
            float f1 = (c1 < in_w) ? Wi[row * in_w + c1] * sc : 0.0f;
            wi[g][k] = pack2(f0, f1);
            wh[g][k] = pack2(Wh[row * 10 + c0] * sc, Wh[row * 10 + c1] * sc);
        }
    }
    // Bias packs: accumulator initializers (bias in lo half, 0 in hi).
    const u64 bRp = pack2(0.5f * (bi[j] + bh[j]), 0.f);
    const u64 bZp = pack2(0.5f * (bi[10 + j] + bh[10 + j]), 0.f);
    const u64 bNp = pack2(bi[20 + j], 0.f);
    const u64 bHp = pack2(bh[20 + j], 0.f);

    // Per-element row pointers (buffer 0; buffer 1 via +IOFF/+HOFF).
    const int ebe0 = lane_ok ? warp * EPW : EPB;
    const float* in_p[EPW];
    const float* rec_p[EPW];
    float*       wr_p[EPW];
#pragma unroll
    for (int e = 0; e < EPW; e++) {
        in_p[e]  = (l == 0) ? &s_x[0][ebe0 + e][0] : &s_h[0][l - 1][ebe0 + e][0];
        rec_p[e] = &s_h[0][l][ebe0 + e][0];
        wr_p[e]  = &s_h[0][l][ebe0 + e][j];
    }
    const int IOFF = (l == 0) ? XOFF : HOFF;

    // x prefetch duty: lanes 0..(EPW*3-1) own (element pe, component pc).
    const bool pf = (lane < EPW * 3);
    const int  pe = lane / 3, pc = lane - pe * 3;
    int egp = blockIdx.x * EPB + warp * EPW + pe;
    if (egp > B - 1) egp = B - 1;
    const float* xg = x + (size_t)egp * (T * 3) + pc;
    float* sxp = &s_x[0][warp * EPW + pe][pc];

    __syncthreads();

    // pipeline init: x[0] -> buf1 (read at s=0); xreg = x[1] (stored during s=0).
    float xreg = 0.0f;
    if (pf) { sxp[XOFF] = xg[0]; xreg = xg[3]; }
    __syncwarp();

    float myh[EPW] = {0.f, 0.f};

    auto step = [&](int s, int bw, bool edge) {
        const int br  = bw ^ 1;
        const int iro = br ? IOFF : 0;
        const int rro = br ? HOFF : 0;
        const int wo  = bw ? HOFF : 0;

        // x staging first (write buffer only read next step, after sync) —
        // R14's predicated 6-lane form (measured better than branchless).
        if (pf) {
            sxp[bw ? XOFF : 0] = xreg;               // stage x[s+1]
            int idx = s + 2; if (idx > T - 1) idx = T - 1;
            xreg = xg[idx * 3];                      // prefetch x[s+2]
        }

        // ---- elem 0: dots + r/z MUFUs; tanh tail deferred past elem 1's dots ----
        float r0, z0, xn0, hh0;
        {
            u64 iv[5], hv[5];
            load10p(in_p[0] + iro, iv);
            load10p(rec_p[0] + rro, hv);
            u64 aR = bRp;
#pragma unroll
            for (int k = 0; k < 5; k++) aR = fma2(wi[0][k], iv[k], aR);
#pragma unroll
            for (int k = 0; k < 5; k++) aR = fma2(wh[0][k], hv[k], aR);
            r0 = sighalf(hsum2(aR));                  // MUFU e0-r in flight
            u64 aZ = bZp;
#pragma unroll
            for (int k = 0; k < 5; k++) aZ = fma2(wi[1][k], iv[k], aZ);
#pragma unroll
            for (int k = 0; k < 5; k++) aZ = fma2(wh[1][k], hv[k], aZ);
            z0 = sighalf(hsum2(aZ));                  // MUFU e0-z in flight
            u64 aN = bNp, aH = bHp;
#pragma unroll
            for (int k = 0; k < 5; k++) {
                aN = fma2(wi[2][k], iv[k], aN);
                aH = fma2(wh[2][k], hv[k], aH);
            }
            xn0 = hsum2(aN);
            hh0 = hsum2(aH);
        }
        // ---- elem 1: dots (e0's MUFU latency hides under this fma stream) ----
        float r1, z1, xn1, hh1;
        {
            u64 iv[5], hv[5];
            load10p(in_p[1] + iro, iv);
            load10p(rec_p[1] + rro, hv);
            u64 aR = bRp;
#pragma unroll
            for (int k = 0; k < 5; k++) aR = fma2(wi[0][k], iv[k], aR);
#pragma unroll
            for (int k = 0; k < 5; k++) aR = fma2(wh[0][k], hv[k], aR);
            r1 = sighalf(hsum2(aR));                  // MUFU e1-r
            u64 aZ = bZp;
#pragma unroll
            for (int k = 0; k < 5; k++) aZ = fma2(wi[1][k], iv[k], aZ);
#pragma unroll
            for (int k = 0; k < 5; k++) aZ = fma2(wh[1][k], hv[k], aZ);
            z1 = sighalf(hsum2(aZ));                  // MUFU e1-z
            u64 aN = bNp, aH = bHp;
#pragma unroll
            for (int k = 0; k < 5; k++) {
                aN = fma2(wi[2][k], iv[k], aN);
                aH = fma2(wh[2][k], hv[k], aH);
            }
            xn1 = hsum2(aN);
            hh1 = hsum2(aH);
        }
        // ---- tails: the two tanhs overlap each other and e1's z MUFU ----
        const float n0 = tanhapx(fmaf(r0, hh0, xn0));
        const float n1 = tanhapx(fmaf(r1, hh1, xn1));
        const float hn0 = n0 + z0 * (myh[0] - n0);
        const float hn1 = n1 + z1 * (myh[1] - n1);
        if (!edge || ((unsigned)(s - l) < (unsigned)T)) {
            myh[0] = hn0;  wr_p[0][wo] = hn0;
            myh[1] = hn1;  wr_p[1][wo] = hn1;
        }
        __syncwarp();
    };

    step(0, 0, true);
    step(1, 1, true);
#pragma unroll 1
    for (int s = 2; s < T; s += 2) {      // s = 2 .. 999, unconditional body
        step(s,     0, false);
        step(s + 1, 1, false);
    }
    step(T,     0, true);                 // s = 1000
    step(T + 1, 1, true);                 // s = 1001 -> final h2 in buffer 1

    // Output head: lanes (l==2, j<EPW) each dot one element's final h2 row.
    if (l == 2 && j < EPW && lane_ok) {
        const int eg = blockIdx.x * EPB + ebe0 + j;
        if (eg < B) {
            const float* hp = rec_p[j] + HOFF;        // s_h[1][2][ebe0+j]
            float acc = bout[0];
#pragma unroll
            for (int k = 0; k < 10; k++) acc = fmaf(Wout[k], hp[k], acc);
            out[eg] = acc;
        }
    }
}

} // namespace

extern "C" void kernel_launch(void* const* d_in, const int* in_sizes, int n_in,
                              void* d_out, int out_size) {
    const float* x    = (const float*)d_in[0];
    const float* Wih0 = (const float*)d_in[1];
    const float* Whh0 = (const float*)d_in[2];
    const float* bih0 = (const float*)d_in[3];
    const float* bhh0 = (const float*)d_in[4];
    const float* Wih1 = (const float*)d_in[5];
    const float* Whh1 = (const float*)d_in[6];
    const float* bih1 = (const float*)d_in[7];
    const float* bhh1 = (const float*)d_in[8];
    const float* Wih2 = (const float*)d_in[9];
    const float* Whh2 = (const float*)d_in[10];
    const float* bih2 = (const float*)d_in[11];
    const float* bhh2 = (const float*)d_in[12];
    const float* Wout = (const float*)d_in[13];
    const float* bout = (const float*)d_in[14];
    float* out = (float*)d_out;

    gru3_pipe2f<<<NBLK, WARPS * 32>>>(x, Wih0, Whh0, bih0, bhh0,
                                      Wih1, Whh1, bih1, bhh1,
                                      Wih2, Whh2, bih2, bhh2,
                                      Wout, bout, out);
}

// round 17
// speedup vs baseline: 1.0314x; 1.0266x over previous
#include <cuda_runtime.h>

namespace {

using u64 = unsigned long long;

constexpr int B  = 4096;
constexpr int T  = 1000;

constexpr int WARPS = 4;             // 128 threads/block
constexpr int EPW   = 2;             // batch elements per warp
constexpr int EPB   = WARPS * EPW;   // 8
constexpr int NBLK  = B / EPB;       // 512 blocks -> 4 blocks/SM binding, single wave
constexpr int RS    = 12;            // padded row stride (floats)
constexpr int EPP   = EPB + EPW;     // 10 rows (layer stride 120 ≡ 24 mod 32: bank-disjoint)

constexpr int HOFF = 3 * EPP * RS;   // 360
constexpr int XOFF = EPP * RS;       // 120

// ---- packed f32x2 helpers ----
__device__ __forceinline__ u64 fma2(u64 a, u64 b, u64 c) {
    u64 d;
    asm("fma.rn.f32x2 %0, %1, %2, %3;" : "=l"(d) : "l"(a), "l"(b), "l"(c));
    return d;
}
__device__ __forceinline__ u64 pack2(float lo, float hi) {
    u64 d;
    asm("mov.b64 %0, {%1, %2};" : "=l"(d) : "f"(lo), "f"(hi));
    return d;
}
__device__ __forceinline__ float hsum2(u64 v) {
    float lo, hi;
    asm("mov.b64 {%0, %1}, %2;" : "=f"(lo), "=f"(hi) : "l"(v));
    return lo + hi;
}
__device__ __forceinline__ float tanhapx(float v) {
    float y;
    asm("tanh.approx.f32 %0, %1;" : "=f"(y) : "f"(v));
    return y;
}
// sigmoid(x) with argument pre-scaled by 0.5 (folded into weights/biases)
__device__ __forceinline__ float sighalf(float a) {
    return fmaf(0.5f, tanhapx(a), 0.5f);
}

__device__ __forceinline__ void load10p(const float* __restrict__ p, u64* v) {
    ulonglong2 a = *reinterpret_cast<const ulonglong2*>(p);
    ulonglong2 b = *reinterpret_cast<const ulonglong2*>(p + 4);
    v[0] = a.x; v[1] = a.y; v[2] = b.x; v[3] = b.y;
    v[4] = *reinterpret_cast<const u64*>(p + 8);
}

__global__ void __launch_bounds__(WARPS * 32, 4)
gru3_pipe2g(const float* __restrict__ x,
            const float* __restrict__ Wih0, const float* __restrict__ Whh0,
            const float* __restrict__ bih0, const float* __restrict__ bhh0,
            const float* __restrict__ Wih1, const float* __restrict__ Whh1,
            const float* __restrict__ bih1, const float* __restrict__ bhh1,
            const float* __restrict__ Wih2, const float* __restrict__ Whh2,
            const float* __restrict__ bih2, const float* __restrict__ bhh2,
            const float* __restrict__ Wout, const float* __restrict__ bout,
            float* __restrict__ out)
{
    __shared__ __align__(16) float s_h[2][3][EPP][RS];
    __shared__ __align__(16) float s_x[2][EPP][RS];

    const int tid  = threadIdx.x;
    const int lane = tid & 31;
    const int warp = tid >> 5;

    int  l = lane / 10;            // layer owned by this lane
    int  j = lane - l * 10;        // hidden unit owned by this lane
    const bool lane_ok = (lane < 30);
    if (!lane_ok) { l = 2; j = 9; }   // dummies: real weights, scratch rows

    for (int idx = tid; idx < 2 * HOFF; idx += WARPS * 32) (&s_h[0][0][0][0])[idx] = 0.0f;
    for (int idx = tid; idx < 2 * XOFF; idx += WARPS * 32) (&s_x[0][0][0])[idx]    = 0.0f;

    // ---- this lane's layer weights -> registers (r/z rows pre-scaled by 0.5) ----
    const float* Wi = (l == 0) ? Wih0 : (l == 1) ? Wih1 : Wih2;
    const float* Wh = (l == 0) ? Whh0 : (l == 1) ? Whh1 : Whh2;
    const float* bi = (l == 0) ? bih0 : (l == 1) ? bih1 : bih2;
    const float* bh = (l == 0) ? bhh0 : (l == 1) ? bhh1 : bhh2;
    const int in_w = (l == 0) ? 3 : 10;

    u64 wi[3][5], wh[3][5];
#pragma unroll
    for (int g = 0; g < 3; g++) {
        const int row = g * 10 + j;
        const float sc = (g < 2) ? 0.5f : 1.0f;
#pragma unroll
        for (int k = 0; k < 5; k++) {
            const int c0 = 2 * k, c1 = 2 * k + 1;
            float f0 = (c0 < in_w) ? Wi[row * in_w + c0] * sc : 0.0f;
            float f1 = (c1 < in_w) ? Wi[row * in_w + c1] * sc : 0.0f;
            wi[g][k] = pack2(f0, f1);
            wh[g][k] = pack2(Wh[row * 10 + c0] * sc, Wh[row * 10 + c1] * sc);
        }
    }
    // Bias packs: accumulator initializers (bias in lo half, 0 in hi).
    const u64 bRp = pack2(0.5f * (bi[j] + bh[j]), 0.f);
    const u64 bZp = pack2(0.5f * (bi[10 + j] + bh[10 + j]), 0.f);
    const u64 bNp = pack2(bi[20 + j], 0.f);
    const u64 bHp = pack2(bh[20 + j], 0.f);

    // Per-element row pointers (buffer 0; buffer 1 via +IOFF/+HOFF).
    const int ebe0 = lane_ok ? warp * EPW : EPB;
    const float* in_p[EPW];
    const float* rec_p[EPW];
    float*       wr_p[EPW];
#pragma unroll
    for (int e = 0; e < EPW; e++) {
        in_p[e]  = (l == 0) ? &s_x[0][ebe0 + e][0] : &s_h[0][l - 1][ebe0 + e][0];
        rec_p[e] = &s_h[0][l][ebe0 + e][0];
        wr_p[e]  = &s_h[0][l][ebe0 + e][j];
    }
    const int IOFF = (l == 0) ? XOFF : HOFF;

    // x prefetch duty: lanes 0..(EPW*3-1) own (element pe, component pc).
    const bool pf = (lane < EPW * 3);
    const int  pe = lane / 3, pc = lane - pe * 3;
    int egp = blockIdx.x * EPB + warp * EPW + pe;
    if (egp > B - 1) egp = B - 1;
    const float* xg = x + (size_t)egp * (T * 3) + pc;
    float* sxp = &s_x[0][warp * EPW + pe][pc];

    __syncthreads();

    // pipeline init: x[0] -> buf1 (read at s=0); xreg = x[1] (stored during s=0).
    float xreg = 0.0f;
    if (pf) { sxp[XOFF] = xg[0]; xreg = xg[3]; }
    __syncwarp();

    float myh[EPW] = {0.f, 0.f};

    auto step = [&](int s, int bw, bool edge) {
        const int br  = bw ^ 1;
        const int iro = br ? IOFF : 0;
        const int rro = br ? HOFF : 0;
        const int wo  = bw ? HOFF : 0;

        // x staging first: write buffer is only read next step (after sync) — legal,
        // and gets the STS off the critical tail.
        if (pf) {
            sxp[bw ? XOFF : 0] = xreg;               // stage x[s+1]
            int idx = s + 2; if (idx > T - 1) idx = T - 1;
            xreg = xg[idx * 3];                      // prefetch x[s+2]
        }

        float hn_out[EPW];
#pragma unroll
        for (int e = 0; e < EPW; e++) {
            u64 iv[5], hv[5];
            load10p(in_p[e]  + iro, iv);
            load10p(rec_p[e] + rro, hv);
            // R gate first -> earliest possible MUFU issue
            u64 aR = bRp;
#pragma unroll
            for (int k = 0; k < 5; k++) aR = fma2(wi[0][k], iv[k], aR);
#pragma unroll
            for (int k = 0; k < 5; k++) aR = fma2(wh[0][k], hv[k], aR);
            const float r = sighalf(hsum2(aR));           // MUFU #1 in flight
            // Z gate next
            u64 aZ = bZp;
#pragma unroll
            for (int k = 0; k < 5; k++) aZ = fma2(wi[1][k], iv[k], aZ);
#pragma unroll
            for (int k = 0; k < 5; k++) aZ = fma2(wh[1][k], hv[k], aZ);
            const float z = sighalf(hsum2(aZ));           // MUFU #2
            // N parts last; n's tanh overlaps the z MUFU
            u64 aN = bNp, aH = bHp;
#pragma unroll
            for (int k = 0; k < 5; k++) {
                aN = fma2(wi[2][k], iv[k], aN);
                aH = fma2(wh[2][k], hv[k], aH);
            }
            const float n = tanhapx(fmaf(r, hsum2(aH), hsum2(aN)));  // MUFU #3
            hn_out[e] = n + z * (myh[e] - n);
        }
        // Deferred stores: no smem store between the two elems' loads/chains above,
        // so ptxas can hoist elem-1 loads and interleave both dependency chains.
#pragma unroll
        for (int e = 0; e < EPW; e++) {
            if (!edge || ((unsigned)(s - l) < (unsigned)T)) {
                myh[e] = hn_out[e];
                wr_p[e][wo] = hn_out[e];
            }
        }
        __syncwarp();
    };

    step(0, 0, true);
    step(1, 1, true);
#pragma unroll 1
    for (int s = 2; s < 998; s += 4) {    // s = 2 .. 997 (996 steps, 4x unrolled)
        step(s,     0, false);
        step(s + 1, 1, false);
        step(s + 2, 0, false);
        step(s + 3, 1, false);
    }
    step(T - 2, 0, false);                // s = 998
    step(T - 1, 1, false);                // s = 999
    step(T,     0, true);                 // s = 1000
    step(T + 1, 1, true);                 // s = 1001 -> final h2 in buffer 1

    // Output head: lanes (l==2, j<EPW) each dot one element's final h2 row.
    if (l == 2 && j < EPW && lane_ok) {
        const int eg = blockIdx.x * EPB + ebe0 + j;
        if (eg < B) {
            const float* hp = rec_p[j] + HOFF;        // s_h[1][2][ebe0+j]
            float acc = bout[0];
#pragma unroll
            for (int k = 0; k < 10; k++) acc = fmaf(Wout[k], hp[k], acc);
            out[eg] = acc;
        }
    }
}

} // namespace

extern "C" void kernel_launch(void* const* d_in, const int* in_sizes, int n_in,
                              void* d_out, int out_size) {
    const float* x    = (const float*)d_in[0];
    const float* Wih0 = (const float*)d_in[1];
    const float* Whh0 = (const float*)d_in[2];
    const float* bih0 = (const float*)d_in[3];
    const float* bhh0 = (const float*)d_in[4];
    const float* Wih1 = (const float*)d_in[5];
    const float* Whh1 = (const float*)d_in[6];
    const float* bih1 = (const float*)d_in[7];
    const float* bhh1 = (const float*)d_in[8];
    const float* Wih2 = (const float*)d_in[9];
    const float* Whh2 = (const float*)d_in[10];
    const float* bih2 = (const float*)d_in[11];
    const float* bhh2 = (const float*)d_in[12];
    const float* Wout = (const float*)d_in[13];
    const float* bout = (const float*)d_in[14];
    float* out = (float*)d_out;

    gru3_pipe2g<<<NBLK, WARPS * 32>>>(x, Wih0, Whh0, bih0, bhh0,
                                      Wih1, Whh1, bih1, bhh1,
                                      Wih2, Whh2, bih2, bhh2,
                                      Wout, bout, out);
}